// round 4
// baseline (speedup 1.0000x reference)
#include <cuda_runtime.h>
#include <cuda_bf16.h>
#include <math.h>
#include <stdint.h>

// ---------------- problem constants ----------------
constexpr int Bv = 8, Tv = 8, Hv = 56, Wv = 56, Cv = 192;
constexpr int NHv = 6, Lv = Hv * Wv;                // 3136
constexpr int HIDv = 4 * Cv;                        // 768
constexpr int Mv = Bv * Tv * Lv;                    // 200704 tokens
constexpr long MCl = (long)Mv * Cv;
constexpr float QSCALE = 0.17677669529663687f;      // 32^-0.5

// ---------------- device scratch ----------------
__device__ float g_mean1[Mv];
__device__ float g_rstd1[Mv];
__device__ float g_mean2t[Mv];
__device__ float g_rstd2t[Mv];
__device__ float g_mean2s[Mv];
__device__ float g_rstd2s[Mv];
__device__ float g_qkv[(long)Mv * 576];
__device__ float g_osp[MCl];
__device__ float g_ot[MCl];
__device__ float g_h[(long)Mv * HIDv];
__device__ float g_xt_fb[MCl];
__device__ float g_xsp_fb[MCl];

// ---------------- helpers ----------------
__device__ __forceinline__ uint32_t smem_u32(const void* p) {
    uint32_t a;
    asm("{ .reg .u64 t; cvta.to.shared.u64 t, %1; cvt.u32.u64 %0, t; }" : "=r"(a) : "l"(p));
    return a;
}

#define LDSM4(r, addr)                                                        \
    asm volatile("ldmatrix.sync.aligned.m8n8.x4.shared.b16 {%0,%1,%2,%3}, [%4];" \
        : "=r"((r)[0]), "=r"((r)[1]), "=r"((r)[2]), "=r"((r)[3]) : "r"(addr))

#define MMA_BF16(c, a, b0, b1)                                                \
    asm volatile("mma.sync.aligned.m16n8k16.row.col.f32.bf16.bf16.f32 "       \
        "{%0,%1,%2,%3},{%4,%5,%6,%7},{%8,%9},{%0,%1,%2,%3};"                  \
        : "+f"((c)[0]), "+f"((c)[1]), "+f"((c)[2]), "+f"((c)[3])              \
        : "r"((a)[0]), "r"((a)[1]), "r"((a)[2]), "r"((a)[3]), "r"(b0), "r"(b1))

// convert float4 -> bf16 hi quad + lo quad, store 8B each (row stride 80B)
__device__ __forceinline__ void cvst80(char* hi, char* lo, int row, int colf, float4 v) {
    uint32_t off = row * 80 + colf * 2;
    uint32_t h01, h23;
    asm("cvt.rn.bf16x2.f32 %0, %1, %2;" : "=r"(h01) : "f"(v.y), "f"(v.x));
    asm("cvt.rn.bf16x2.f32 %0, %1, %2;" : "=r"(h23) : "f"(v.w), "f"(v.z));
    float r0 = v.x - __uint_as_float(h01 << 16);
    float r1 = v.y - __uint_as_float(h01 & 0xFFFF0000u);
    float r2 = v.z - __uint_as_float(h23 << 16);
    float r3 = v.w - __uint_as_float(h23 & 0xFFFF0000u);
    uint32_t l01, l23;
    asm("cvt.rn.bf16x2.f32 %0, %1, %2;" : "=r"(l01) : "f"(r1), "f"(r0));
    asm("cvt.rn.bf16x2.f32 %0, %1, %2;" : "=r"(l23) : "f"(r3), "f"(r2));
    *reinterpret_cast<uint2*>(hi + off) = make_uint2(h01, h23);
    *reinterpret_cast<uint2*>(lo + off) = make_uint2(l01, l23);
}

// ---------------- mma.sync fused GEMM ----------------
// Y[M,N] = epi( f(A)[M,KD] @ W[N,KD]^T + bias )
// grid: blockIdx.x = COLUMN tile (fast-varying -> A tile L2 reuse), blockIdx.y = row tile
// AM: 0 plain, 1 layernorm, 2 concat(A|A2); EM: 0 bias, 1 +qscale, 2 +residual, 3 +GELU
constexpr int STAGE = 30720;   // Ahi 0 | Alo 10240 | Bhi 20480 | Blo 25600 (80B rows)
constexpr int DSMEM = 2 * STAGE;

template <int KD, int AM, int EM>
__global__ void __launch_bounds__(256, 2)
mma_gemm(const float* __restrict__ A, const float* __restrict__ A2,
         const float* __restrict__ W, const float* __restrict__ bias,
         const float* __restrict__ mean, const float* __restrict__ rstd,
         const float* __restrict__ gamma, const float* __restrict__ beta,
         const float* __restrict__ R, float* __restrict__ Y, int N) {
    extern __shared__ char sm[];
    const int tid = threadIdx.x;
    const long m0 = (long)blockIdx.y * 128;
    const int n0 = blockIdx.x * 64;
    constexpr int NS = KD / 32;

    // loader mapping
    const int ar = tid >> 1, ac = (tid & 1) * 16;   // A: 2 thr/row, 4 float4 each
    const int br = tid >> 2, bc = (tid & 3) * 8;    // B: 4 thr/row, 2 float4 each
    float mu = 0.f, rsd = 0.f;
    if (AM == 1) { mu = mean[m0 + ar]; rsd = rstd[m0 + ar]; }

    float4 pa[4], pb[2];
    auto gload = [&](int s) {
        const int kg = s * 32;
#pragma unroll
        for (int j = 0; j < 4; j++) {
            int col = kg + ac + j * 4;
            const float* src;
            if (AM == 2) src = (col < 192) ? A + (m0 + ar) * 192 + col
                                           : A2 + (m0 + ar) * 192 + (col - 192);
            else         src = A + (m0 + ar) * (long)KD + col;
            float4 v = *reinterpret_cast<const float4*>(src);
            if (AM == 1) {
                float4 g4 = *reinterpret_cast<const float4*>(gamma + col);
                float4 b4 = *reinterpret_cast<const float4*>(beta + col);
                v.x = (v.x - mu) * rsd * g4.x + b4.x;
                v.y = (v.y - mu) * rsd * g4.y + b4.y;
                v.z = (v.z - mu) * rsd * g4.z + b4.z;
                v.w = (v.w - mu) * rsd * g4.w + b4.w;
            }
            pa[j] = v;
        }
#pragma unroll
        for (int j = 0; j < 2; j++)
            pb[j] = *reinterpret_cast<const float4*>(W + (long)(n0 + br) * KD + kg + bc + j * 4);
    };
    auto sstore = [&](int buf) {
        char* base = sm + buf * STAGE;
#pragma unroll
        for (int j = 0; j < 4; j++) cvst80(base, base + 10240, ar, ac + j * 4, pa[j]);
#pragma unroll
        for (int j = 0; j < 2; j++) cvst80(base + 20480, base + 25600, br, bc + j * 4, pb[j]);
    };

    // mma mapping: 8 warps = 4(M) x 2(N); warp tile 32x32
    const int l = tid & 31, wid = tid >> 5;
    const int wm = wid & 3, wn = wid >> 2;
    const int arow = wm * 32 + (l & 15);
    const int acol8 = (l >> 4) * 8;
    const int brow = wn * 32 + (l & 7) + ((l >> 4) << 3);
    const int bcol8 = ((l >> 3) & 1) * 8;
    const uint32_t smb = smem_u32(sm);

    float acc[2][4][4];
#pragma unroll
    for (int i = 0; i < 2; i++)
#pragma unroll
        for (int j = 0; j < 4; j++)
#pragma unroll
            for (int k = 0; k < 4; k++) acc[i][j][k] = 0.f;

    auto mmastage = [&](int buf) {
        const uint32_t base = smb + buf * STAGE;
#pragma unroll
        for (int kt = 0; kt < 2; kt++) {
            uint32_t ah[2][4], alr[2][4], bh[2][4], blr[2][4];
#pragma unroll
            for (int mt = 0; mt < 2; mt++) {
                uint32_t addr = base + (arow + mt * 16) * 80 + (kt * 16 + acol8) * 2;
                LDSM4(ah[mt], addr);
                LDSM4(alr[mt], addr + 10240);
            }
#pragma unroll
            for (int nt = 0; nt < 2; nt++) {
                uint32_t addr = base + 20480 + (brow + nt * 16) * 80 + (kt * 16 + bcol8) * 2;
                LDSM4(bh[nt], addr);
                LDSM4(blr[nt], addr + 5120);
            }
#pragma unroll
            for (int mt = 0; mt < 2; mt++)
#pragma unroll
                for (int nn = 0; nn < 4; nn++) {
                    const int nt = nn >> 1, jj = nn & 1;
                    MMA_BF16(acc[mt][nn], ah[mt], bh[nt][2 * jj], bh[nt][2 * jj + 1]);
                    MMA_BF16(acc[mt][nn], ah[mt], blr[nt][2 * jj], blr[nt][2 * jj + 1]);
                    MMA_BF16(acc[mt][nn], alr[mt], bh[nt][2 * jj], bh[nt][2 * jj + 1]);
                }
        }
    };

    gload(0); sstore(0);
    gload(1);
    __syncthreads();
    for (int s = 0; s < NS; s++) {
        mmastage(s & 1);
        __syncthreads();
        if (s + 1 < NS) {
            sstore((s + 1) & 1);
            if (s + 2 < NS) gload(s + 2);
            __syncthreads();
        }
    }

    // register epilogue
    const int g = l >> 2, tg = l & 3;
#pragma unroll
    for (int mt = 0; mt < 2; mt++)
#pragma unroll
        for (int nn = 0; nn < 4; nn++) {
            const int col = n0 + wn * 32 + nn * 8 + 2 * tg;
            const float b0 = bias[col], b1 = bias[col + 1];
#pragma unroll
            for (int h = 0; h < 2; h++) {
                const long row = m0 + wm * 32 + mt * 16 + g + 8 * h;
                float vx = acc[mt][nn][2 * h] + b0;
                float vy = acc[mt][nn][2 * h + 1] + b1;
                if (EM == 1) {
                    if (col < 192) { vx *= QSCALE; vy *= QSCALE; }
                }
                if (EM == 2) {
                    float2 rv = *reinterpret_cast<const float2*>(R + row * (long)N + col);
                    vx += rv.x; vy += rv.y;
                }
                if (EM == 3) {
                    vx = 0.5f * vx * (1.0f + erff(vx * 0.70710678118654752f));
                    vy = 0.5f * vy * (1.0f + erff(vy * 0.70710678118654752f));
                }
                *reinterpret_cast<float2*>(Y + row * (long)N + col) = make_float2(vx, vy);
            }
        }
}

// ---------------- LN statistics ----------------
__global__ void ln_stats_kernel(const float* __restrict__ X,
                                float* __restrict__ mean, float* __restrict__ rstd) {
    int tok = blockIdx.x * 8 + (threadIdx.x >> 5);
    int lane = threadIdx.x & 31;
    const float* p = X + (long)tok * Cv;
    float v[6];
#pragma unroll
    for (int i = 0; i < 6; i++) v[i] = p[lane + i * 32];
    float s = v[0] + v[1] + v[2] + v[3] + v[4] + v[5];
#pragma unroll
    for (int o = 16; o > 0; o >>= 1) s += __shfl_xor_sync(~0u, s, o);
    float mu = s * (1.0f / Cv);
    float qv = 0.f;
#pragma unroll
    for (int i = 0; i < 6; i++) { float d = v[i] - mu; qv += d * d; }
#pragma unroll
    for (int o = 16; o > 0; o >>= 1) qv += __shfl_xor_sync(~0u, qv, o);
    if (lane == 0) {
        mean[tok] = mu;
        rstd[tok] = rsqrtf(qv * (1.0f / Cv) + 1e-5f);
    }
}

// ---------------- spatial window attention (1x4 column blocking) ----------------
__global__ void __launch_bounds__(128) attn_spatial_kernel(const float* __restrict__ qkv,
                                                           float* __restrict__ osp) {
    __shared__ float qs[49][33], ks[49][33], vs[49][33];
    __shared__ float sc[49][52];
    const int gh = blockIdx.x;
    const int g = gh / 6, h = gh % 6;
    const int b = g >> 9;
    const int rem = g & 511;
    const int win = rem >> 3, t = rem & 7;
    const int wh = win >> 3, ww = win & 7;
    const int tid = threadIdx.x;
    const long frame = (long)(b * 8 + t) * Lv;

    for (int idx = tid; idx < 49 * 32; idx += 128) {
        int i = idx >> 5, j = idx & 31;
        int l = (wh * 7 + i / 7) * 56 + ww * 7 + (i % 7);
        long base = (frame + l) * 576 + h * 32 + j;
        qs[i][j] = qkv[base];
        ks[i][j] = qkv[base + 192];
        vs[i][j] = qkv[base + 384];
    }
    __syncthreads();

    // scores: thread computes 4 adjacent cols of one row (reuse q operand)
    for (int u = tid; u < 49 * 13; u += 128) {
        int i = u / 13, jb = (u % 13) * 4;
        float a0 = 0.f, a1 = 0.f, a2 = 0.f, a3 = 0.f;
        int j1 = jb + 1 < 49 ? jb + 1 : 48;
        int j2 = jb + 2 < 49 ? jb + 2 : 48;
        int j3 = jb + 3 < 49 ? jb + 3 : 48;
#pragma unroll
        for (int kk = 0; kk < 32; kk++) {
            float qv = qs[i][kk];
            a0 += qv * ks[jb][kk];
            a1 += qv * ks[j1][kk];
            a2 += qv * ks[j2][kk];
            a3 += qv * ks[j3][kk];
        }
        sc[i][jb] = a0;
        if (jb + 1 < 49) sc[i][jb + 1] = a1;
        if (jb + 2 < 49) sc[i][jb + 2] = a2;
        if (jb + 3 < 49) sc[i][jb + 3] = a3;
    }
    __syncthreads();

    if (tid < 49) {
        float mx = -1e30f;
#pragma unroll 7
        for (int j = 0; j < 49; j++) mx = fmaxf(mx, sc[tid][j]);
        float sum = 0.f;
#pragma unroll 7
        for (int j = 0; j < 49; j++) { float e = __expf(sc[tid][j] - mx); sc[tid][j] = e; sum += e; }
        float inv = 1.0f / sum;
#pragma unroll 7
        for (int j = 0; j < 49; j++) sc[tid][j] *= inv;
    }
    __syncthreads();

    // AV: thread computes 4 adjacent channels of one row (reuse score operand)
    for (int u = tid; u < 49 * 8; u += 128) {
        int i = u >> 3, jb = (u & 7) * 4;
        float a0 = 0.f, a1 = 0.f, a2 = 0.f, a3 = 0.f;
#pragma unroll
        for (int n = 0; n < 49; n++) {
            float s = sc[i][n];
            a0 += s * vs[n][jb + 0];
            a1 += s * vs[n][jb + 1];
            a2 += s * vs[n][jb + 2];
            a3 += s * vs[n][jb + 3];
        }
        int l = (wh * 7 + i / 7) * 56 + ww * 7 + (i % 7);
        *reinterpret_cast<float4*>(&osp[(frame + l) * 192 + h * 32 + jb]) =
            make_float4(a0, a1, a2, a3);
    }
}

// ---------------- temporal attention: row-wise softmax, no spills ----------------
__global__ void __launch_bounds__(256) attn_temporal_kernel(const float* __restrict__ qkv,
                                                            float* __restrict__ ot) {
    const int unit = blockIdx.x * 8 + (threadIdx.x >> 5);
    const int lane = threadIdx.x & 31;
    const int g = unit / 6, h = unit % 6;
    const int b = g / Lv, l = g % Lv;
    const long base0 = ((long)(b * 8) * Lv + l) * 576 + h * 32 + lane;
    const long tstride = (long)Lv * 576;

    float q[8], k[8], v[8];
#pragma unroll
    for (int t = 0; t < 8; t++) {
        long base = base0 + (long)t * tstride;
        q[t] = qkv[base];
        k[t] = qkv[base + 192];
        v[t] = qkv[base + 384];
    }
#pragma unroll
    for (int t1 = 0; t1 < 8; t1++) {
        float s[8];
#pragma unroll
        for (int t2 = 0; t2 < 8; t2++) s[t2] = q[t1] * k[t2];
        // batched butterflies (ILP across the 8 reductions)
#pragma unroll
        for (int o = 16; o > 0; o >>= 1) {
#pragma unroll
            for (int t2 = 0; t2 < 8; t2++) s[t2] += __shfl_xor_sync(~0u, s[t2], o);
        }
        float mx = s[0];
#pragma unroll
        for (int t2 = 1; t2 < 8; t2++) mx = fmaxf(mx, s[t2]);
        float sum = 0.f;
#pragma unroll
        for (int t2 = 0; t2 < 8; t2++) { s[t2] = __expf(s[t2] - mx); sum += s[t2]; }
        float inv = 1.0f / sum;
        float o = 0.f;
#pragma unroll
        for (int t2 = 0; t2 < 8; t2++) o += s[t2] * v[t2];
        ot[((long)(b * 8 + t1) * Lv + l) * 192 + h * 32 + lane] = o * inv;
    }
}

// ---------------- launcher ----------------
extern "C" void kernel_launch(void* const* d_in, const int* in_sizes, int n_in,
                              void* d_out, int out_size) {
    (void)in_sizes; (void)n_in;
    const float* x        = (const float*)d_in[0];
    const float* norm1_g  = (const float*)d_in[2];
    const float* norm1_b  = (const float*)d_in[3];
    const float* qkv_w    = (const float*)d_in[4];
    const float* qkv_b    = (const float*)d_in[5];
    const float* proj_sp_w = (const float*)d_in[6];
    const float* proj_sp_b = (const float*)d_in[7];
    const float* proj_t_w = (const float*)d_in[8];
    const float* proj_t_b = (const float*)d_in[9];
    const float* norm2_g  = (const float*)d_in[10];
    const float* norm2_b  = (const float*)d_in[11];
    const float* te_fc1_w = (const float*)d_in[12];
    const float* te_fc1_b = (const float*)d_in[13];
    const float* te_fc2_w = (const float*)d_in[14];
    const float* te_fc2_b = (const float*)d_in[15];
    const float* sp_fc1_w = (const float*)d_in[16];
    const float* sp_fc1_b = (const float*)d_in[17];
    const float* sp_fc2_w = (const float*)d_in[18];
    const float* sp_fc2_b = (const float*)d_in[19];
    const float* fuse_w   = (const float*)d_in[20];
    const float* fuse_b   = (const float*)d_in[21];

    float* out = (float*)d_out;
    float *xt, *xsp;
    if ((long)out_size >= 3 * MCl) {
        xt = out + MCl;
        xsp = out + 2 * MCl;
    } else {
        void* p;
        cudaGetSymbolAddress(&p, g_xt_fb);  xt = (float*)p;
        cudaGetSymbolAddress(&p, g_xsp_fb); xsp = (float*)p;
    }
    void* p;
    cudaGetSymbolAddress(&p, g_qkv);    float* qkv = (float*)p;
    cudaGetSymbolAddress(&p, g_osp);    float* osp = (float*)p;
    cudaGetSymbolAddress(&p, g_ot);     float* otb = (float*)p;
    cudaGetSymbolAddress(&p, g_h);      float* hbuf = (float*)p;
    cudaGetSymbolAddress(&p, g_mean1);  float* mean1 = (float*)p;
    cudaGetSymbolAddress(&p, g_rstd1);  float* rstd1 = (float*)p;
    cudaGetSymbolAddress(&p, g_mean2t); float* mean2t = (float*)p;
    cudaGetSymbolAddress(&p, g_rstd2t); float* rstd2t = (float*)p;
    cudaGetSymbolAddress(&p, g_mean2s); float* mean2s = (float*)p;
    cudaGetSymbolAddress(&p, g_rstd2s); float* rstd2s = (float*)p;

    cudaFuncSetAttribute(mma_gemm<192, 1, 1>, cudaFuncAttributeMaxDynamicSharedMemorySize, DSMEM);
    cudaFuncSetAttribute(mma_gemm<192, 0, 2>, cudaFuncAttributeMaxDynamicSharedMemorySize, DSMEM);
    cudaFuncSetAttribute(mma_gemm<192, 1, 3>, cudaFuncAttributeMaxDynamicSharedMemorySize, DSMEM);
    cudaFuncSetAttribute(mma_gemm<768, 0, 2>, cudaFuncAttributeMaxDynamicSharedMemorySize, DSMEM);
    cudaFuncSetAttribute(mma_gemm<384, 2, 0>, cudaFuncAttributeMaxDynamicSharedMemorySize, DSMEM);

    const int MT = Mv / 128;  // 1568  (grid: x = column tile for L2 reuse of A)

    // 1) LN1 stats
    ln_stats_kernel<<<Mv / 8, 256>>>(x, mean1, rstd1);
    // 2) QKV = LN1(x) @ qkv_w^T + b (q pre-scaled)
    mma_gemm<192, 1, 1><<<dim3(9, MT), 256, DSMEM>>>(
        x, nullptr, qkv_w, qkv_b, mean1, rstd1, norm1_g, norm1_b, nullptr, qkv, 576);
    // 3) spatial attention
    attn_spatial_kernel<<<4096 * 6, 128>>>(qkv, osp);
    // 4) temporal attention
    attn_temporal_kernel<<<(Bv * Lv * 6) / 8, 256>>>(qkv, otb);
    // 5) x_sp = osp @ proj_sp^T + b + x
    mma_gemm<192, 0, 2><<<dim3(3, MT), 256, DSMEM>>>(
        osp, nullptr, proj_sp_w, proj_sp_b, nullptr, nullptr, nullptr, nullptr, x, xsp, 192);
    // 6) x_t = ot @ proj_t^T + b + x
    mma_gemm<192, 0, 2><<<dim3(3, MT), 256, DSMEM>>>(
        otb, nullptr, proj_t_w, proj_t_b, nullptr, nullptr, nullptr, nullptr, x, xt, 192);
    // 7) LN2 stats
    ln_stats_kernel<<<Mv / 8, 256>>>(xt, mean2t, rstd2t);
    ln_stats_kernel<<<Mv / 8, 256>>>(xsp, mean2s, rstd2s);
    // 8) temporal MLP
    mma_gemm<192, 1, 3><<<dim3(12, MT), 256, DSMEM>>>(
        xt, nullptr, te_fc1_w, te_fc1_b, mean2t, rstd2t, norm2_g, norm2_b, nullptr, hbuf, HIDv);
    mma_gemm<768, 0, 2><<<dim3(3, MT), 256, DSMEM>>>(
        hbuf, nullptr, te_fc2_w, te_fc2_b, nullptr, nullptr, nullptr, nullptr, xt, xt, 192);
    // 9) spatial MLP
    mma_gemm<192, 1, 3><<<dim3(12, MT), 256, DSMEM>>>(
        xsp, nullptr, sp_fc1_w, sp_fc1_b, mean2s, rstd2s, norm2_g, norm2_b, nullptr, hbuf, HIDv);
    mma_gemm<768, 0, 2><<<dim3(3, MT), 256, DSMEM>>>(
        hbuf, nullptr, sp_fc2_w, sp_fc2_b, nullptr, nullptr, nullptr, nullptr, xsp, xsp, 192);
    // 10) out = [xt | xsp] @ fuse_w^T + fuse_b
    mma_gemm<384, 2, 0><<<dim3(3, MT), 256, DSMEM>>>(
        xt, xsp, fuse_w, fuse_b, nullptr, nullptr, nullptr, nullptr, nullptr, out, 192);
}